// round 12
// baseline (speedup 1.0000x reference)
#include <cuda_runtime.h>
#include <cuda_bf16.h>
#include <cstdint>

// MaxUnpooling2D scatter-add: geometric phases {1,1,2,4,8} batches,
// scatter kernels INTERLEAVED across the origin stream and the single side
// stream so wave-quantization tails backfill each other.
// updates: [16,128,128,64] f32   d_in[0]
// mask:    [16,128,128,64] int32 d_in[1], values in [0, 1<<22)
// out:     [16,256,256,64] f32   (256 MB)
//
// sZ (hi-prio): Z0 Z1 Z2 Z3 Z4  p1  p3      (p1/p3 ordered after their zeros)
// origin:       [evZ0] p0  [evZ2] p2  [evZ4] p4   [join evS]

static constexpr int OUT_FLAT      = 1 << 22;   // floats per batch
static constexpr int GRP_PER_BATCH = 1 << 18;   // float4-groups per batch
static constexpr int NPHASE        = 5;
__host__ __device__ constexpr int phase_start(int p)   { return (p == 0) ? 0 : (1 << (p - 1)); }
__host__ __device__ constexpr int phase_batches(int p) { return (p == 0) ? 1 : (1 << (p - 1)); }

__global__ __launch_bounds__(256)
void zero_phase(float4* __restrict__ w) {
    unsigned i = blockIdx.x * 256u + threadIdx.x;
    w[i] = make_float4(0.f, 0.f, 0.f, 0.f);
}

// One float4-group (4 spread REDG) per thread; base = first group index.
__global__ __launch_bounds__(256)
void scatter_phase(const float4* __restrict__ up,
                   const int4*   __restrict__ mk,
                   float*        __restrict__ out,
                   unsigned base) {
    unsigned g = base + blockIdx.x * 256u + threadIdx.x;
    float* outb = out + ((size_t)(g >> 18) << 22);   // per-batch window
    float4 u = up[g];
    int4   m = mk[g];
    atomicAdd(outb + m.x, u.x);
    atomicAdd(outb + m.y, u.y);
    atomicAdd(outb + m.z, u.z);
    atomicAdd(outb + m.w, u.w);
}

extern "C" void kernel_launch(void* const* d_in, const int* in_sizes, int n_in,
                              void* d_out, int out_size) {
    const float4* up  = (const float4*)d_in[0];
    const int4*   mk  = (const int4*)d_in[1];
    float*        out = (float*)d_out;

    // Exactly ONE extra stream (R10 showed >1 trips the allocation guard).
    // High priority so zero CTAs win placement against resident scatters.
    int loPrio = 0, hiPrio = 0;
    cudaDeviceGetStreamPriorityRange(&loPrio, &hiPrio);
    cudaStream_t sZ;
    cudaStreamCreateWithPriority(&sZ, cudaStreamNonBlocking, hiPrio);

    cudaEvent_t evFork;
    cudaEventCreateWithFlags(&evFork, cudaEventDisableTiming);
    cudaEventRecord(evFork, 0);
    cudaStreamWaitEvent(sZ, evFork, 0);

    // sZ: zero all windows (phase order), recording an event per window.
    cudaEvent_t evZ[NPHASE];
    for (int p = 0; p < NPHASE; p++) {
        float4* w = (float4*)(out + (size_t)phase_start(p) * OUT_FLAT);
        unsigned nf4 = (unsigned)phase_batches(p) * (OUT_FLAT / 4);
        zero_phase<<<nf4 / 256, 256, 0, sZ>>>(w);
        cudaEventCreateWithFlags(&evZ[p], cudaEventDisableTiming);
        cudaEventRecord(evZ[p], sZ);
    }

    // Launch helper
    auto scatter = [&](int p, cudaStream_t s) {
        unsigned base   = (unsigned)phase_start(p) * GRP_PER_BATCH;
        unsigned groups = (unsigned)phase_batches(p) * GRP_PER_BATCH;
        scatter_phase<<<groups / 256, 256, 0, s>>>(up, mk, out, base);
    };

    // origin: p0, p2, p4 (each gated on its window's zero event).
    // sZ:     p1, p3     (ordered after their zeros by stream order).
    cudaStreamWaitEvent(0, evZ[0], 0); scatter(0, 0);
    scatter(1, sZ);
    cudaStreamWaitEvent(0, evZ[2], 0); scatter(2, 0);
    scatter(3, sZ);
    cudaStreamWaitEvent(0, evZ[4], 0); scatter(4, 0);

    // Join sZ back into origin.
    cudaEvent_t evS;
    cudaEventCreateWithFlags(&evS, cudaEventDisableTiming);
    cudaEventRecord(evS, sZ);
    cudaStreamWaitEvent(0, evS, 0);
}

// round 14
// speedup vs baseline: 1.1562x; 1.1562x over previous
#include <cuda_runtime.h>
#include <cuda_bf16.h>
#include <cstdint>

// MaxUnpooling2D scatter-add: ONE fused kernel, self-paced zero->scatter
// pipeline, no phases/tails/lead-in.
// updates: [16,128,128,64] f32   d_in[0]
// mask:    [16,128,128,64] int32 d_in[1], values in [0, 1<<22)
// out:     [16,256,256,64] f32   (256 MB)
//
// CTA bid (group g = bid>>10):
//   1. unconditionally zero 16KB chunk (bid+1024) -> batch g+1
//      (group 0 additionally zeroes chunk bid -> batch 0)
//   2. fence + bump per-batch zero counter
//   3. gate: spin until counter[g] == 1024 (providers have LOWER bids ->
//      resident earlier -> deadlock-free; batch 0 self-contained in wave 1)
//   4. scatter 256 float4-groups (4 REDs each)
// Last CTA to finish resets counters (deterministic across graph replays).

static constexpr int NCTA           = 16384;    // 4M groups / 256
static constexpr int CTAS_PER_BATCH = 1024;
static constexpr int F4_PER_CHUNK   = 1024;     // 16KB chunk = 1024 float4

__device__ unsigned g_zcnt[16];
__device__ unsigned g_fin;

__global__ __launch_bounds__(256, 8)
void unpool_fused(const float4* __restrict__ up,
                  const int4*   __restrict__ mk,
                  float*        __restrict__ out)
{
    const unsigned bid = blockIdx.x;
    const int      tx  = threadIdx.x;
    const unsigned b   = bid >> 10;               // my scatter batch

    // ---- 1. Unconditional zeroing (fire-and-forget STG.128) ----
    const float4 zv = make_float4(0.f, 0.f, 0.f, 0.f);
    if (bid < 1024) {                             // prologue: batch 0 (self)
        float4* w = (float4*)out + (size_t)bid * F4_PER_CHUNK;
        #pragma unroll
        for (int j = 0; j < 4; j++) w[j * 256 + tx] = zv;
    }
    if (bid < NCTA - 1024) {                      // batch g+1 chunk
        float4* w = (float4*)out + (size_t)(bid + 1024) * F4_PER_CHUNK;
        #pragma unroll
        for (int j = 0; j < 4; j++) w[j * 256 + tx] = zv;
    }
    __syncthreads();
    if (tx == 0) {
        __threadfence();                          // release zero stores
        if (bid < 1024)        atomicAdd(&g_zcnt[0], 1u);
        if (bid < NCTA - 1024) atomicAdd(&g_zcnt[b + 1], 1u);
    }

    // ---- 3. Gate on my batch's zero completion ----
    if (tx == 0) {
        volatile unsigned* p = &g_zcnt[b];
        if (*p < CTAS_PER_BATCH) {
            unsigned ns = 32;
            do { __nanosleep(ns); if (ns < 512) ns <<= 1; }
            while (*p < CTAS_PER_BATCH);
        }
    }
    __syncthreads();

    // ---- 4. Scatter: one float4-group per thread (4 spread REDG) ----
    {
        unsigned g = bid * 256u + tx;
        float* outb = out + ((size_t)b << 22);
        float4 u = up[g];
        int4   m = mk[g];
        atomicAdd(outb + m.x, u.x);
        atomicAdd(outb + m.y, u.y);
        atomicAdd(outb + m.z, u.z);
        atomicAdd(outb + m.w, u.w);
    }

    // ---- Reset state for next graph replay (last CTA does it) ----
    __syncthreads();
    if (tx == 0) {
        unsigned v = atomicAdd(&g_fin, 1u);
        if (v == NCTA - 1) {                      // I'm the last CTA
            #pragma unroll
            for (int i = 0; i < 16; i++) g_zcnt[i] = 0;
            g_fin = 0;
            __threadfence();
        }
    }
}

extern "C" void kernel_launch(void* const* d_in, const int* in_sizes, int n_in,
                              void* d_out, int out_size) {
    const float4* up  = (const float4*)d_in[0];
    const int4*   mk  = (const int4*)d_in[1];
    float*        out = (float*)d_out;

    unpool_fused<<<NCTA, 256>>>(up, mk, out);
}